// round 1
// baseline (speedup 1.0000x reference)
#include <cuda_runtime.h>
#include <math.h>

#define BDIM 4
#define CDIM 512
#define HWD 4096
#define HIDD 256

// ---------------- scratch (device globals; allocation-free) ----------------
__device__ float g_mvn_c[(size_t)BDIM * CDIM * HWD];
__device__ float g_mvn_s[(size_t)BDIM * CDIM * HWD];
__device__ float g_Fq[(size_t)BDIM * CDIM * HWD];
__device__ float g_Gk[(size_t)BDIM * CDIM * HWD];
__device__ float g_Hv[(size_t)BDIM * CDIM * HWD];
__device__ float g_Obuf[(size_t)BDIM * CDIM * HWD];
__device__ float g_rn_c[(size_t)BDIM * HWD];
__device__ float g_rn_s[(size_t)BDIM * HWD];
__device__ float g_S[(size_t)BDIM * HWD * HWD];     // 268 MB
__device__ float g_A[(size_t)BDIM * HWD * HWD];     // 268 MB
__device__ float g_hmid[(size_t)BDIM * HWD * HIDD];
__device__ float g_clamp[(size_t)BDIM * HWD];

// ---------------- mvn: per (b,c) mean/var(ddof=1) norm over 4096 ----------------
__global__ void mvn_kernel(const float* __restrict__ x, float* __restrict__ y) {
    int bc = blockIdx.x;
    const float* px = x + (size_t)bc * HWD;
    float* py = y + (size_t)bc * HWD;
    int t = threadIdx.x;
    float s = 0.f, s2 = 0.f;
    for (int i = t; i < HWD; i += 256) { float v = px[i]; s += v; s2 += v * v; }
    __shared__ float r1[256], r2[256];
    r1[t] = s; r2[t] = s2; __syncthreads();
    for (int o = 128; o > 0; o >>= 1) {
        if (t < o) { r1[t] += r1[t + o]; r2[t] += r2[t + o]; }
        __syncthreads();
    }
    float mean = r1[0] * (1.0f / HWD);
    float var = (r2[0] - (float)HWD * mean * mean) * (1.0f / (HWD - 1));
    float inv = rsqrtf(var + 1e-5f);
    for (int i = t; i < HWD; i += 256) py[i] = (px[i] - mean) * inv;
}

// ---------------- reciprocal channel-L2 norm per (b, position) ----------------
__global__ void rnorm_kernel(const float* __restrict__ x, float* __restrict__ rn) {
    int b = blockIdx.y;
    int k = blockIdx.x * 256 + threadIdx.x;
    const float* px = x + (size_t)b * CDIM * HWD + k;
    float s = 0.f;
#pragma unroll 8
    for (int c = 0; c < CDIM; c++) { float v = px[(size_t)c * HWD]; s += v * v; }
    float n = sqrtf(s);
    rn[b * HWD + k] = 1.0f / fmaxf(n, 1e-12f);
}

// ---------------- psi: clamp[b,k] = sigmoid(hmid_row . W2 + b2)*0.5 + 0.4 ----------------
__global__ void psi_kernel(const float* __restrict__ hmid, const float* __restrict__ W2,
                           const float* __restrict__ b2, float* __restrict__ clampv) {
    int row = blockIdx.x * 4 + (threadIdx.x >> 5);
    int lane = threadIdx.x & 31;
    const float* p = hmid + (size_t)row * HIDD;
    float s = 0.f;
#pragma unroll
    for (int j = lane; j < HIDD; j += 32) s += p[j] * W2[j];
#pragma unroll
    for (int o = 16; o > 0; o >>= 1) s += __shfl_xor_sync(0xffffffffu, s, o);
    if (lane == 0) {
        float psi = 1.f / (1.f + __expf(-(s + b2[0])));
        clampv[row] = psi * 0.5f + 0.4f;
    }
}

// ---------------- softmax over row + gated sigmoid, in place ----------------
__global__ void softgate_kernel(float* __restrict__ S, const float* __restrict__ clampv) {
    size_t row = blockIdx.x;
    float* p = S + row * HWD;
    __shared__ float buf[HWD];
    __shared__ float red[256];
    int t = threadIdx.x;
    float mx = -1e30f;
    for (int i = t; i < HWD; i += 256) { float v = p[i]; buf[i] = v; mx = fmaxf(mx, v); }
    red[t] = mx; __syncthreads();
    for (int o = 128; o > 0; o >>= 1) { if (t < o) red[t] = fmaxf(red[t], red[t + o]); __syncthreads(); }
    mx = red[0]; __syncthreads();
    float sum = 0.f;
    for (int i = t; i < HWD; i += 256) { float e = __expf(buf[i] - mx); buf[i] = e; sum += e; }
    red[t] = sum; __syncthreads();
    for (int o = 128; o > 0; o >>= 1) { if (t < o) red[t] += red[t + o]; __syncthreads(); }
    float inv = 1.0f / red[0];
    float cv = clampv[row];
    for (int i = t; i < HWD; i += 256) {
        float x = buf[i] * inv;
        p[i] = 1.0f / (1.0f + __expf(-50.0f * (x - cv)));
    }
}

// ---------------- generic 128x128x8 SGEMM ----------------
// A logically MxK: A_KM=true  -> stored [K,M] (idx k*lda+m), else [M,K] (idx m*lda+k)
// B logically KxN: B_NK=true  -> stored [N,K] (idx n*ldb+k), else [K,N] (idx k*ldb+n)
// epilogue: v = acc*scaleM[m]*scaleN[n] + bias(m|n); act; + addSrc; store
template <bool A_KM, bool B_NK>
__global__ __launch_bounds__(256)
void sgemm_kernel(const float* __restrict__ A, const float* __restrict__ B, float* __restrict__ C,
                  int M, int N, int K, int lda, int ldb, int ldc,
                  long long sA, long long sB, long long sC,
                  const float* __restrict__ bias, int biasMode,
                  const float* __restrict__ scaleM, long long sSM,
                  const float* __restrict__ scaleN, long long sSN,
                  const float* __restrict__ addSrc, long long sAdd,
                  int actMode) {
    __shared__ float As[8][128];
    __shared__ float Bs[8][128];
    int bz = blockIdx.z;
    A += sA * bz; B += sB * bz;
    float* Cb = C + sC * bz;
    int bm = blockIdx.y * 128, bn = blockIdx.x * 128;
    int tid = threadIdx.x;
    int tx = tid & 15, ty = tid >> 4;
    int row0 = ty * 8, col0 = tx * 8;
    float acc[8][8];
#pragma unroll
    for (int i = 0; i < 8; i++)
#pragma unroll
        for (int j = 0; j < 8; j++) acc[i][j] = 0.f;

    for (int k0 = 0; k0 < K; k0 += 8) {
        if (A_KM) {
            int kk = tid >> 5, mm = (tid & 31) << 2;
            float4 v = *(const float4*)(A + (size_t)(k0 + kk) * lda + bm + mm);
            *(float4*)&As[kk][mm] = v;
        } else {
            int mm = tid >> 1, kk = (tid & 1) << 2;
            float4 v = *(const float4*)(A + (size_t)(bm + mm) * lda + k0 + kk);
            As[kk + 0][mm] = v.x; As[kk + 1][mm] = v.y; As[kk + 2][mm] = v.z; As[kk + 3][mm] = v.w;
        }
        if (!B_NK) {
            int kk = tid >> 5, nn = (tid & 31) << 2;
            float4 v = *(const float4*)(B + (size_t)(k0 + kk) * ldb + bn + nn);
            *(float4*)&Bs[kk][nn] = v;
        } else {
            int nn = tid >> 1, kk = (tid & 1) << 2;
            float4 v = *(const float4*)(B + (size_t)(bn + nn) * ldb + k0 + kk);
            Bs[kk + 0][nn] = v.x; Bs[kk + 1][nn] = v.y; Bs[kk + 2][nn] = v.z; Bs[kk + 3][nn] = v.w;
        }
        __syncthreads();
#pragma unroll
        for (int kk = 0; kk < 8; kk++) {
            float a[8], bb[8];
#pragma unroll
            for (int i = 0; i < 8; i++) a[i] = As[kk][row0 + i];
#pragma unroll
            for (int j = 0; j < 8; j++) bb[j] = Bs[kk][col0 + j];
#pragma unroll
            for (int i = 0; i < 8; i++)
#pragma unroll
                for (int j = 0; j < 8; j++) acc[i][j] = fmaf(a[i], bb[j], acc[i][j]);
        }
        __syncthreads();
    }

#pragma unroll
    for (int i = 0; i < 8; i++) {
        int m = bm + row0 + i;
        float sm = scaleM ? scaleM[sSM * bz + m] : 1.f;
        float bm_add = (biasMode == 1) ? bias[m] : 0.f;
#pragma unroll
        for (int j = 0; j < 8; j++) {
            int n = bn + col0 + j;
            float v = acc[i][j] * sm;
            if (scaleN) v *= scaleN[sSN * bz + n];
            v += bm_add;
            if (biasMode == 2) v += bias[n];
            if (actMode == 1) v = (v > 0.f) ? v : 0.2f * v;
            if (addSrc) v += addSrc[sAdd * bz + (size_t)m * ldc + n];
            Cb[(size_t)m * ldc + n] = v;
        }
    }
}

// ---------------- host launcher ----------------
extern "C" void kernel_launch(void* const* d_in, const int* in_sizes, int n_in,
                              void* d_out, int out_size) {
    const float* content = (const float*)d_in[0];
    const float* style   = (const float*)d_in[1];
    const float* Wf   = (const float*)d_in[2];
    const float* bf   = (const float*)d_in[3];
    const float* Wg   = (const float*)d_in[4];
    const float* bg   = (const float*)d_in[5];
    const float* Wh   = (const float*)d_in[6];
    const float* bh   = (const float*)d_in[7];
    const float* Wout = (const float*)d_in[8];
    const float* bout = (const float*)d_in[9];
    const float* W1   = (const float*)d_in[10];
    const float* b1   = (const float*)d_in[11];
    const float* W2   = (const float*)d_in[12];
    const float* b2   = (const float*)d_in[13];
    float* out = (float*)d_out;

    float *mvnC, *mvnS, *Fq, *Gk, *Hv, *Obuf, *rnC, *rnS, *S, *Amat, *hmid, *clampv;
    cudaGetSymbolAddress((void**)&mvnC, g_mvn_c);
    cudaGetSymbolAddress((void**)&mvnS, g_mvn_s);
    cudaGetSymbolAddress((void**)&Fq, g_Fq);
    cudaGetSymbolAddress((void**)&Gk, g_Gk);
    cudaGetSymbolAddress((void**)&Hv, g_Hv);
    cudaGetSymbolAddress((void**)&Obuf, g_Obuf);
    cudaGetSymbolAddress((void**)&rnC, g_rn_c);
    cudaGetSymbolAddress((void**)&rnS, g_rn_s);
    cudaGetSymbolAddress((void**)&S, g_S);
    cudaGetSymbolAddress((void**)&Amat, g_A);
    cudaGetSymbolAddress((void**)&hmid, g_hmid);
    cudaGetSymbolAddress((void**)&clampv, g_clamp);

    const long long CS = (long long)CDIM * HWD;        // per-batch stride, [C,HW] tensors
    const long long SS = (long long)HWD * HWD;         // per-batch stride, [HW,HW] tensors
    const long long HS = (long long)HWD * HIDD;        // per-batch stride, hmid

    // 1) mean-variance norms
    mvn_kernel<<<BDIM * CDIM, 256>>>(content, mvnC);
    mvn_kernel<<<BDIM * CDIM, 256>>>(style, mvnS);

    // 2) reciprocal channel-L2 norms
    rnorm_kernel<<<dim3(HWD / 256, BDIM), 256>>>(content, rnC);
    rnorm_kernel<<<dim3(HWD / 256, BDIM), 256>>>(style, rnS);

    // 3) conv1x1 GEMMs: [512,512] @ [512,4096] per batch  (NN)
    dim3 gConv(HWD / 128, CDIM / 128, BDIM);
    sgemm_kernel<false, false><<<gConv, 256>>>(Wf, mvnC, Fq, CDIM, HWD, CDIM, CDIM, HWD, HWD,
        0, CS, CS, bf, 1, nullptr, 0, nullptr, 0, nullptr, 0, 0);
    sgemm_kernel<false, false><<<gConv, 256>>>(Wg, mvnS, Gk, CDIM, HWD, CDIM, CDIM, HWD, HWD,
        0, CS, CS, bg, 1, nullptr, 0, nullptr, 0, nullptr, 0, 0);
    sgemm_kernel<false, false><<<gConv, 256>>>(Wh, style, Hv, CDIM, HWD, CDIM, CDIM, HWD, HWD,
        0, CS, CS, bh, 1, nullptr, 0, nullptr, 0, nullptr, 0, 0);

    // 4) attention logits: S[k,l] = Fq^T Gk   (TN, K=512)
    dim3 gBig(HWD / 128, HWD / 128, BDIM);
    sgemm_kernel<true, false><<<gBig, 256>>>(Fq, Gk, S, HWD, HWD, CDIM, HWD, HWD, HWD,
        CS, CS, SS, nullptr, 0, nullptr, 0, nullptr, 0, nullptr, 0, 0);

    // 5) affinity: A[k,l] = rn_c[k]*rn_s[l] * content^T style  (TN, K=512)
    sgemm_kernel<true, false><<<gBig, 256>>>(content, style, Amat, HWD, HWD, CDIM, HWD, HWD, HWD,
        CS, CS, SS, nullptr, 0, rnC, HWD, rnS, HWD, nullptr, 0, 0);

    // 6) hmid = leaky_relu(A @ W1^T + b1)  (NT, M=4096,N=256,K=4096)
    dim3 gHmid(HIDD / 128, HWD / 128, BDIM);
    sgemm_kernel<false, true><<<gHmid, 256>>>(Amat, W1, hmid, HWD, HIDD, HWD, HWD, HWD, HIDD,
        SS, 0, HS, b1, 2, nullptr, 0, nullptr, 0, nullptr, 0, 1);

    // 7) psi -> clamp values
    psi_kernel<<<BDIM * HWD / 4, 128>>>(hmid, W2, b2, clampv);

    // 8) softmax + gating (in place on S)
    softgate_kernel<<<BDIM * HWD, 256>>>(S, clampv);

    // 9) O = Hv @ Sg^T  (NT, M=512,N=4096,K=4096)
    dim3 gO(HWD / 128, CDIM / 128, BDIM);
    sgemm_kernel<false, true><<<gO, 256>>>(Hv, S, Obuf, CDIM, HWD, HWD, HWD, HWD, HWD,
        CS, SS, CS, nullptr, 0, nullptr, 0, nullptr, 0, nullptr, 0, 0);

    // 10) out = Wout @ O + bout + content  (NN)
    sgemm_kernel<false, false><<<gConv, 256>>>(Wout, Obuf, out, CDIM, HWD, CDIM, CDIM, HWD, HWD,
        0, CS, CS, bout, 1, nullptr, 0, nullptr, 0, content, CS, 0);
}

// round 2
// speedup vs baseline: 1.3625x; 1.3625x over previous
#include <cuda_runtime.h>
#include <math.h>

#define BDIM 4
#define CDIM 512
#define HWD 4096
#define HIDD 256

// ---------------- scratch (device globals; allocation-free) ----------------
__device__ float g_mvn_c[(size_t)BDIM * CDIM * HWD];
__device__ float g_mvn_s[(size_t)BDIM * CDIM * HWD];
__device__ float g_Fq[(size_t)BDIM * CDIM * HWD];
__device__ float g_Gk[(size_t)BDIM * CDIM * HWD];
__device__ float g_Hv[(size_t)BDIM * CDIM * HWD];
__device__ float g_Obuf[(size_t)BDIM * CDIM * HWD];
__device__ float g_rn_c[(size_t)BDIM * HWD];
__device__ float g_rn_s[(size_t)BDIM * HWD];
__device__ float g_S[(size_t)BDIM * HWD * HWD];     // 268 MB
__device__ float g_A[(size_t)BDIM * HWD * HWD];     // 268 MB
__device__ float g_hmid[(size_t)BDIM * HWD * HIDD];
__device__ float g_clamp[(size_t)BDIM * HWD];

// ---------------- small helpers ----------------
__device__ __forceinline__ unsigned f2tf(float x) {
    unsigned r;
    asm("cvt.rna.tf32.f32 %0, %1;" : "=r"(r) : "f"(x));
    return r;
}

__device__ __forceinline__ void mma8(float* d, const unsigned* a, const unsigned* b) {
    asm volatile(
        "mma.sync.aligned.m16n8k8.row.col.f32.tf32.tf32.f32 "
        "{%0,%1,%2,%3},{%4,%5,%6,%7},{%8,%9},{%0,%1,%2,%3};"
        : "+f"(d[0]), "+f"(d[1]), "+f"(d[2]), "+f"(d[3])
        : "r"(a[0]), "r"(a[1]), "r"(a[2]), "r"(a[3]), "r"(b[0]), "r"(b[1]));
}

// ---------------- mvn: per (b,c) mean/var(ddof=1) norm over 4096 ----------------
__global__ void mvn_kernel(const float* __restrict__ x, float* __restrict__ y) {
    int bc = blockIdx.x;
    const float* px = x + (size_t)bc * HWD;
    float* py = y + (size_t)bc * HWD;
    int t = threadIdx.x;
    float s = 0.f, s2 = 0.f;
    for (int i = t; i < HWD; i += 256) { float v = px[i]; s += v; s2 += v * v; }
    __shared__ float r1[256], r2[256];
    r1[t] = s; r2[t] = s2; __syncthreads();
    for (int o = 128; o > 0; o >>= 1) {
        if (t < o) { r1[t] += r1[t + o]; r2[t] += r2[t + o]; }
        __syncthreads();
    }
    float mean = r1[0] * (1.0f / HWD);
    float var = (r2[0] - (float)HWD * mean * mean) * (1.0f / (HWD - 1));
    float inv = rsqrtf(var + 1e-5f);
    for (int i = t; i < HWD; i += 256) py[i] = (px[i] - mean) * inv;
}

// ---------------- reciprocal channel-L2 norm per (b, position) ----------------
__global__ void rnorm_kernel(const float* __restrict__ x, float* __restrict__ rn) {
    int b = blockIdx.y;
    int k = blockIdx.x * 256 + threadIdx.x;
    const float* px = x + (size_t)b * CDIM * HWD + k;
    float s = 0.f;
#pragma unroll 8
    for (int c = 0; c < CDIM; c++) { float v = px[(size_t)c * HWD]; s += v * v; }
    float n = sqrtf(s);
    rn[b * HWD + k] = 1.0f / fmaxf(n, 1e-12f);
}

// ---------------- psi: clamp[b,k] = sigmoid(hmid_row . W2 + b2)*0.5 + 0.4 ----------------
__global__ void psi_kernel(const float* __restrict__ hmid, const float* __restrict__ W2,
                           const float* __restrict__ b2, float* __restrict__ clampv) {
    int row = blockIdx.x * 4 + (threadIdx.x >> 5);
    int lane = threadIdx.x & 31;
    const float* p = hmid + (size_t)row * HIDD;
    float s = 0.f;
#pragma unroll
    for (int j = lane; j < HIDD; j += 32) s += p[j] * W2[j];
#pragma unroll
    for (int o = 16; o > 0; o >>= 1) s += __shfl_xor_sync(0xffffffffu, s, o);
    if (lane == 0) {
        float psi = 1.f / (1.f + __expf(-(s + b2[0])));
        clampv[row] = psi * 0.5f + 0.4f;
    }
}

// ---------------- softmax over row + gated sigmoid, in place ----------------
__global__ void softgate_kernel(float* __restrict__ S, const float* __restrict__ clampv) {
    size_t row = blockIdx.x;
    float* p = S + row * HWD;
    __shared__ float buf[HWD];
    __shared__ float red[256];
    int t = threadIdx.x;
    float mx = -1e30f;
    for (int i = t; i < HWD; i += 256) { float v = p[i]; buf[i] = v; mx = fmaxf(mx, v); }
    red[t] = mx; __syncthreads();
    for (int o = 128; o > 0; o >>= 1) { if (t < o) red[t] = fmaxf(red[t], red[t + o]); __syncthreads(); }
    mx = red[0]; __syncthreads();
    float sum = 0.f;
    for (int i = t; i < HWD; i += 256) { float e = __expf(buf[i] - mx); buf[i] = e; sum += e; }
    red[t] = sum; __syncthreads();
    for (int o = 128; o > 0; o >>= 1) { if (t < o) red[t] += red[t + o]; __syncthreads(); }
    float inv = 1.0f / red[0];
    float cv = clampv[row];
    for (int i = t; i < HWD; i += 256) {
        float x = buf[i] * inv;
        p[i] = 1.0f / (1.0f + __expf(-50.0f * (x - cv)));
    }
}

// ---------------- tf32 tensor-core GEMM, 128x128 tile, BK=16, double-buffered ----
// A logically MxK: A_KM=true -> stored [K,M], else [M,K]
// B logically KxN: B_NK=true -> stored [N,K], else [K,N]
// SPLIT: 3xTF32 error compensation (near-fp32 accuracy)
// smem tile layout: [k][c] with row stride 136 floats (conflict-free for frag LDS)

template <bool KM>
__device__ __forceinline__ void ldg_tile(const float* __restrict__ P, int ld, int k0, int c0,
                                         float4 (&r)[2], int t) {
#pragma unroll
    for (int i = 0; i < 2; i++) {
        int f = i * 256 + t;
        if (KM) {
            int kk = f >> 5, cc = (f & 31) << 2;
            r[i] = *(const float4*)(P + (size_t)(k0 + kk) * ld + c0 + cc);
        } else {
            int cc = f >> 2, kk = (f & 3) << 2;
            r[i] = *(const float4*)(P + (size_t)(c0 + cc) * ld + k0 + kk);
        }
    }
}

template <bool KM>
__device__ __forceinline__ void sts_tile(float (*S)[136], const float4 (&r)[2], int t) {
#pragma unroll
    for (int i = 0; i < 2; i++) {
        int f = i * 256 + t;
        if (KM) {
            int kk = f >> 5, cc = (f & 31) << 2;
            *(float4*)&S[kk][cc] = r[i];
        } else {
            int cc = f >> 2, kk = (f & 3) << 2;
            S[kk + 0][cc] = r[i].x; S[kk + 1][cc] = r[i].y;
            S[kk + 2][cc] = r[i].z; S[kk + 3][cc] = r[i].w;
        }
    }
}

template <bool A_KM, bool B_NK, bool SPLIT>
__global__ __launch_bounds__(256)
void tc_gemm(const float* __restrict__ A, const float* __restrict__ B, float* __restrict__ C,
             int M, int N, int K, int lda, int ldb, int ldc,
             long long sA, long long sB, long long sC,
             const float* __restrict__ bias, int biasMode,
             const float* __restrict__ scaleM, long long sSM,
             const float* __restrict__ scaleN, long long sSN,
             const float* __restrict__ addSrc, long long sAdd,
             int actMode) {
    __shared__ float As[2][16][136];
    __shared__ float Bs[2][16][136];
    int bz = blockIdx.z;
    A += sA * bz; B += sB * bz;
    float* Cb = C + sC * bz;
    int bm = blockIdx.y * 128, bn = blockIdx.x * 128;
    int t = threadIdx.x, w = t >> 5, lane = t & 31;
    int wm = (w >> 1) * 32, wn = (w & 1) * 64;
    int g = lane >> 2, tg = lane & 3;

    float acc[2][8][4];
#pragma unroll
    for (int mi = 0; mi < 2; mi++)
#pragma unroll
        for (int ni = 0; ni < 8; ni++)
#pragma unroll
            for (int r = 0; r < 4; r++) acc[mi][ni][r] = 0.f;

    float4 rA[2], rB[2];
    ldg_tile<A_KM>(A, lda, 0, bm, rA, t);
    ldg_tile<!B_NK>(B, ldb, 0, bn, rB, t);
    sts_tile<A_KM>(As[0], rA, t);
    sts_tile<!B_NK>(Bs[0], rB, t);
    __syncthreads();

    int T = K / 16, p = 0;
    for (int kt = 0; kt < T; kt++) {
        if (kt + 1 < T) {
            ldg_tile<A_KM>(A, lda, (kt + 1) * 16, bm, rA, t);
            ldg_tile<!B_NK>(B, ldb, (kt + 1) * 16, bn, rB, t);
        }
#pragma unroll
        for (int ks = 0; ks < 16; ks += 8) {
            unsigned ah[2][4], al[2][4];
            unsigned bh[8][2], bl[8][2];
#pragma unroll
            for (int mi = 0; mi < 2; mi++) {
                int m0 = wm + mi * 16;
                float f0 = As[p][ks + tg][m0 + g];
                float f1 = As[p][ks + tg][m0 + g + 8];
                float f2 = As[p][ks + tg + 4][m0 + g];
                float f3 = As[p][ks + tg + 4][m0 + g + 8];
                ah[mi][0] = f2tf(f0); ah[mi][1] = f2tf(f1);
                ah[mi][2] = f2tf(f2); ah[mi][3] = f2tf(f3);
                if (SPLIT) {
                    al[mi][0] = f2tf(f0 - __uint_as_float(ah[mi][0]));
                    al[mi][1] = f2tf(f1 - __uint_as_float(ah[mi][1]));
                    al[mi][2] = f2tf(f2 - __uint_as_float(ah[mi][2]));
                    al[mi][3] = f2tf(f3 - __uint_as_float(ah[mi][3]));
                }
            }
#pragma unroll
            for (int ni = 0; ni < 8; ni++) {
                int n0 = wn + ni * 8 + g;
                float f0 = Bs[p][ks + tg][n0];
                float f1 = Bs[p][ks + tg + 4][n0];
                bh[ni][0] = f2tf(f0); bh[ni][1] = f2tf(f1);
                if (SPLIT) {
                    bl[ni][0] = f2tf(f0 - __uint_as_float(bh[ni][0]));
                    bl[ni][1] = f2tf(f1 - __uint_as_float(bh[ni][1]));
                }
            }
#pragma unroll
            for (int mi = 0; mi < 2; mi++)
#pragma unroll
                for (int ni = 0; ni < 8; ni++) {
                    mma8(acc[mi][ni], ah[mi], bh[ni]);
                    if (SPLIT) {
                        mma8(acc[mi][ni], ah[mi], bl[ni]);
                        mma8(acc[mi][ni], al[mi], bh[ni]);
                    }
                }
        }
        if (kt + 1 < T) {
            p ^= 1;
            sts_tile<A_KM>(As[p], rA, t);
            sts_tile<!B_NK>(Bs[p], rB, t);
            __syncthreads();
        }
    }

    // epilogue
#pragma unroll
    for (int mi = 0; mi < 2; mi++) {
#pragma unroll
        for (int ni = 0; ni < 8; ni++) {
#pragma unroll
            for (int half = 0; half < 2; half++) {
                int m = bm + wm + mi * 16 + g + half * 8;
                int n = bn + wn + ni * 8 + 2 * tg;
                float v0 = acc[mi][ni][half * 2 + 0];
                float v1 = acc[mi][ni][half * 2 + 1];
                if (scaleM) { float s = scaleM[sSM * bz + m]; v0 *= s; v1 *= s; }
                if (scaleN) { v0 *= scaleN[sSN * bz + n]; v1 *= scaleN[sSN * bz + n + 1]; }
                if (biasMode == 1) { float b = bias[m]; v0 += b; v1 += b; }
                if (biasMode == 2) { v0 += bias[n]; v1 += bias[n + 1]; }
                if (actMode == 1) {
                    v0 = (v0 > 0.f) ? v0 : 0.2f * v0;
                    v1 = (v1 > 0.f) ? v1 : 0.2f * v1;
                }
                if (addSrc) {
                    v0 += addSrc[sAdd * bz + (size_t)m * ldc + n];
                    v1 += addSrc[sAdd * bz + (size_t)m * ldc + n + 1];
                }
                float2 ov = make_float2(v0, v1);
                *(float2*)(Cb + (size_t)m * ldc + n) = ov;
            }
        }
    }
}

// ---------------- host launcher ----------------
extern "C" void kernel_launch(void* const* d_in, const int* in_sizes, int n_in,
                              void* d_out, int out_size) {
    const float* content = (const float*)d_in[0];
    const float* style   = (const float*)d_in[1];
    const float* Wf   = (const float*)d_in[2];
    const float* bf   = (const float*)d_in[3];
    const float* Wg   = (const float*)d_in[4];
    const float* bg   = (const float*)d_in[5];
    const float* Wh   = (const float*)d_in[6];
    const float* bh   = (const float*)d_in[7];
    const float* Wout = (const float*)d_in[8];
    const float* bout = (const float*)d_in[9];
    const float* W1   = (const float*)d_in[10];
    const float* b1   = (const float*)d_in[11];
    const float* W2   = (const float*)d_in[12];
    const float* b2   = (const float*)d_in[13];
    float* out = (float*)d_out;

    float *mvnC, *mvnS, *Fq, *Gk, *Hv, *Obuf, *rnC, *rnS, *S, *Amat, *hmid, *clampv;
    cudaGetSymbolAddress((void**)&mvnC, g_mvn_c);
    cudaGetSymbolAddress((void**)&mvnS, g_mvn_s);
    cudaGetSymbolAddress((void**)&Fq, g_Fq);
    cudaGetSymbolAddress((void**)&Gk, g_Gk);
    cudaGetSymbolAddress((void**)&Hv, g_Hv);
    cudaGetSymbolAddress((void**)&Obuf, g_Obuf);
    cudaGetSymbolAddress((void**)&rnC, g_rn_c);
    cudaGetSymbolAddress((void**)&rnS, g_rn_s);
    cudaGetSymbolAddress((void**)&S, g_S);
    cudaGetSymbolAddress((void**)&Amat, g_A);
    cudaGetSymbolAddress((void**)&hmid, g_hmid);
    cudaGetSymbolAddress((void**)&clampv, g_clamp);

    const long long CS = (long long)CDIM * HWD;
    const long long SS = (long long)HWD * HWD;
    const long long HS = (long long)HWD * HIDD;

    // 1) mean-variance norms
    mvn_kernel<<<BDIM * CDIM, 256>>>(content, mvnC);
    mvn_kernel<<<BDIM * CDIM, 256>>>(style, mvnS);

    // 2) reciprocal channel-L2 norms
    rnorm_kernel<<<dim3(HWD / 256, BDIM), 256>>>(content, rnC);
    rnorm_kernel<<<dim3(HWD / 256, BDIM), 256>>>(style, rnS);

    // 3) conv1x1 GEMMs: W[512,512] @ X[512,4096] per batch (A: [M][K], B: [K][N])
    dim3 gConv(HWD / 128, CDIM / 128, BDIM);
    tc_gemm<false, false, true><<<gConv, 256>>>(Wf, mvnC, Fq, CDIM, HWD, CDIM, CDIM, HWD, HWD,
        0, CS, CS, bf, 1, nullptr, 0, nullptr, 0, nullptr, 0, 0);
    tc_gemm<false, false, true><<<gConv, 256>>>(Wg, mvnS, Gk, CDIM, HWD, CDIM, CDIM, HWD, HWD,
        0, CS, CS, bg, 1, nullptr, 0, nullptr, 0, nullptr, 0, 0);
    tc_gemm<false, false, true><<<gConv, 256>>>(Wh, style, Hv, CDIM, HWD, CDIM, CDIM, HWD, HWD,
        0, CS, CS, bh, 1, nullptr, 0, nullptr, 0, nullptr, 0, 0);

    // 4) attention logits: S = Fq^T Gk  (A stored [K,M], SPLIT for gate precision)
    dim3 gBig(HWD / 128, HWD / 128, BDIM);
    tc_gemm<true, false, true><<<gBig, 256>>>(Fq, Gk, S, HWD, HWD, CDIM, HWD, HWD, HWD,
        CS, CS, SS, nullptr, 0, nullptr, 0, nullptr, 0, nullptr, 0, 0);

    // 5) affinity: A = rn_c ⊗ rn_s * content^T style  (plain tf32 — clamp path, damped)
    tc_gemm<true, false, false><<<gBig, 256>>>(content, style, Amat, HWD, HWD, CDIM, HWD, HWD, HWD,
        CS, CS, SS, nullptr, 0, rnC, HWD, rnS, HWD, nullptr, 0, 0);

    // 6) hmid = leaky_relu(A @ W1^T + b1)  (plain tf32)
    dim3 gHmid(HIDD / 128, HWD / 128, BDIM);
    tc_gemm<false, true, false><<<gHmid, 256>>>(Amat, W1, hmid, HWD, HIDD, HWD, HWD, HWD, HIDD,
        SS, 0, HS, b1, 2, nullptr, 0, nullptr, 0, nullptr, 0, 1);

    // 7) psi -> clamp values
    psi_kernel<<<BDIM * HWD / 4, 128>>>(hmid, W2, b2, clampv);

    // 8) softmax + gating (in place on S)
    softgate_kernel<<<BDIM * HWD, 256>>>(S, clampv);

    // 9) O = Hv @ Sg^T  (SPLIT — output path)
    dim3 gO(HWD / 128, CDIM / 128, BDIM);
    tc_gemm<false, true, true><<<gO, 256>>>(Hv, S, Obuf, CDIM, HWD, HWD, HWD, HWD, HWD,
        CS, SS, CS, nullptr, 0, nullptr, 0, nullptr, 0, nullptr, 0, 0);

    // 10) out = Wout @ O + bout + content  (SPLIT — output path)
    tc_gemm<false, false, true><<<gConv, 256>>>(Wout, Obuf, out, CDIM, HWD, CDIM, CDIM, HWD, HWD,
        0, CS, CS, bout, 1, nullptr, 0, nullptr, 0, content, CS, 0);
}